// round 11
// baseline (speedup 1.0000x reference)
#include <cuda_runtime.h>
#include <stdint.h>

// =============================================================================
// key32 = int32-wrapped reference key: (b&3)<<30 | x<<20 | y<<10 | z.
// Packed hash entry (8B): key32<<32 | index. atomicMin == min-index per key.
// EMPTY 0xFF..F unreachable (key bit 29 always 0 for coords < 512).
//
// Pipeline (graph fork-join):
//   stream B: merged_copy rows [0, Nsplit)      (no deps -> overlaps A)
//   stream A: clear -> build -> row join
//   join     : feat = pruned+scaled all rows, merged[:,2:] rows >= Nsplit
// =============================================================================

#define MASK_CAP (1u << 22)
#define DS_CAP   (1u << 19)
#define EMPTY64  0xFFFFFFFFFFFFFFFFull

__device__ unsigned long long g_mtab[MASK_CAP];
__device__ unsigned long long g_dtab[DS_CAP];
__device__ float2             g_rowinfo[1100000];

__device__ __forceinline__ uint32_t key32_of(int4 c) {
    return ((uint32_t)c.x << 30) | ((uint32_t)c.y << 20) |
           ((uint32_t)c.z << 10) | (uint32_t)c.w;
}

__device__ __forceinline__ uint32_t hash32(uint32_t k) {
    k ^= k >> 16; k *= 0x85ebca6bu;
    k ^= k >> 13; k *= 0xc2b2ae35u;
    k ^= k >> 16;
    return k;
}

__global__ void clear_all(float* __restrict__ dsm, int Nd) {
    int t = blockIdx.x * blockDim.x + threadIdx.x;
    int stride = gridDim.x * blockDim.x;
    ulonglong2 ff = make_ulonglong2(EMPTY64, EMPTY64);
    for (int s = t; s < (int)(MASK_CAP / 2); s += stride)
        ((ulonglong2*)g_mtab)[s] = ff;
    for (int s = t; s < (int)(DS_CAP / 2); s += stride)
        ((ulonglong2*)g_dtab)[s] = ff;
    float4 z = make_float4(0.f, 0.f, 0.f, 0.f);
    for (int s = t; s < Nd / 4; s += stride)
        ((float4*)dsm)[s] = z;
    int tail = (Nd / 4) * 4;
    if (t < Nd - tail) dsm[tail + t] = 0.f;
}

__device__ __forceinline__ void insert(unsigned long long* __restrict__ tab,
                                       uint32_t k, int i, uint32_t capmask) {
    unsigned long long desired = ((unsigned long long)k << 32) | (uint32_t)i;
    uint32_t slot = hash32(k) & capmask;
    while (true) {
        unsigned long long prev = atomicCAS(&tab[slot], EMPTY64, desired);
        if (prev == EMPTY64) break;
        if ((uint32_t)(prev >> 32) == k) {
            atomicMin(&tab[slot], desired);
            break;
        }
        slot = (slot + 1) & capmask;
    }
}

__global__ void build_all(const int4* __restrict__ mask_coords, int M,
                          const int4* __restrict__ ds_coords, int Nd,
                          int mblocks) {
    if ((int)blockIdx.x < mblocks) {
        int i = blockIdx.x * blockDim.x + threadIdx.x;
        if (i >= M) return;
        insert(g_mtab, key32_of(mask_coords[i]), i, MASK_CAP - 1);
    } else {
        int i = (blockIdx.x - mblocks) * blockDim.x + threadIdx.x;
        if (i >= Nd) return;
        insert(g_dtab, key32_of(ds_coords[i]), i, DS_CAP - 1);
    }
}

// ---- Early merged-feature copy (rows [0, Nsplit)) -- runs on forked stream
__global__ void merged_copy(const float4* __restrict__ x_feats,
                            float* __restrict__ merged,
                            int Nsplit, int VC, int C) {
    long long t = (long long)blockIdx.x * blockDim.x + threadIdx.x;
    long long total = (long long)Nsplit * VC;
    if (t >= total) return;
    int i = (int)(t / VC);
    int j = (int)(t % VC);
    float4 f = x_feats[t];
    float2* m = (float2*)(merged + (size_t)i * (size_t)(C + 2) + 2 + (size_t)j * 4);
    m[0] = make_float2(f.x, f.y);
    m[1] = make_float2(f.z, f.w);
}

__global__ void row_kernel(const int4* __restrict__ x_coords,
                           const float2* __restrict__ mask_scores,
                           float* __restrict__ merged,
                           float* __restrict__ ds_mask,
                           int N, int C) {
    int i = blockIdx.x * blockDim.x + threadIdx.x;
    if (i >= N) return;
    int4 c = x_coords[i];
    uint32_t k = key32_of(c);
    float s0 = 0.0f, s1 = 0.0f;
    uint32_t slot = hash32(k) & (MASK_CAP - 1);
    while (true) {
        unsigned long long e = __ldg(&g_mtab[slot]);
        if ((uint32_t)(e >> 32) == k) {
            float2 msv = __ldg(&mask_scores[(uint32_t)e]);
            s0 = msv.x; s1 = msv.y;
            break;
        }
        if (e == EMPTY64) break;
        slot = (slot + 1) & (MASK_CAP - 1);
    }
    float attn = (s1 > 0.5f) ? 1.0f : 0.0f;
    g_rowinfo[i] = make_float2(attn, s1 * attn);
    *(float2*)(merged + (size_t)i * (size_t)(C + 2)) = make_float2(s0, s1);
    if (attn > 0.0f) {
        int4 p = make_int4(c.x, c.y >> 1, c.z >> 1, c.w >> 1);
        uint32_t pk = key32_of(p);
        uint32_t ds = hash32(pk) & (DS_CAP - 1);
        while (true) {
            unsigned long long e = __ldg(&g_dtab[ds]);
            if ((uint32_t)(e >> 32) == pk) { ds_mask[(uint32_t)e] = 1.0f; break; }
            if (e == EMPTY64) break;
            ds = (ds + 1) & (DS_CAP - 1);
        }
    }
}

// ---- Main stream kernel: pruned+scaled all rows; merged only i >= Nsplit --
__global__ void feat_kernel(const float4* __restrict__ x_feats,
                            float4* __restrict__ pruned,
                            float4* __restrict__ scaled,
                            float* __restrict__ merged,
                            int N, int VC, int C, int Nsplit) {
    long long t = (long long)blockIdx.x * blockDim.x + threadIdx.x;
    long long total = (long long)N * VC;
    if (t >= total) return;
    int i = (int)(t / VC);
    int j = (int)(t % VC);
    float4 f = x_feats[t];
    float2 rs = g_rowinfo[i];
    pruned[t] = make_float4(f.x * rs.x, f.y * rs.x, f.z * rs.x, f.w * rs.x);
    scaled[t] = make_float4(f.x * rs.y, f.y * rs.y, f.z * rs.y, f.w * rs.y);
    if (i >= Nsplit) {
        float2* m = (float2*)(merged + (size_t)i * (size_t)(C + 2) + 2
                              + (size_t)j * 4);
        m[0] = make_float2(f.x, f.y);
        m[1] = make_float2(f.z, f.w);
    }
}

// ---------------- Launch ----------------------------------------------------
extern "C" void kernel_launch(void* const* d_in, const int* in_sizes, int n_in,
                              void* d_out, int out_size) {
    const int4*   x_coords    = (const int4*)d_in[0];
    const float*  x_feats     = (const float*)d_in[1];
    const int4*   mask_coords = (const int4*)d_in[2];
    const float2* mask_scores = (const float2*)d_in[3];
    const int4*   ds_coords   = (const int4*)d_in[4];

    int N  = in_sizes[0] / 4;
    int C  = in_sizes[1] / N;
    int M  = in_sizes[2] / 4;
    int Nd = in_sizes[4] / 4;
    int VC = C / 4;

    float* out    = (float*)d_out;
    float* pruned = out;
    float* scaled = out + (size_t)N * C;
    float* merged = out + (size_t)2 * N * C;
    float* dsm    = merged + (size_t)N * (C + 2);

    // One-time stream/event handles (no device-memory allocation involved;
    // identical launch pattern every call -> deterministic captured graph).
    static cudaStream_t s_b = nullptr;
    static cudaEvent_t  e_fork = nullptr, e_join = nullptr;
    if (s_b == nullptr) {
        cudaStreamCreateWithFlags(&s_b, cudaStreamNonBlocking);
        cudaEventCreateWithFlags(&e_fork, cudaEventDisableTiming);
        cudaEventCreateWithFlags(&e_join, cudaEventDisableTiming);
    }

    const int B = 256;
    int Nsplit = (N / 2) & ~63;

    // Fork: early merged copy for rows [0, Nsplit) on stream B.
    cudaEventRecord(e_fork, 0);
    cudaStreamWaitEvent(s_b, e_fork, 0);
    {
        long long tB = (long long)Nsplit * VC;
        int gB = (int)((tB + B - 1) / B);
        merged_copy<<<gB, B, 0, s_b>>>((const float4*)x_feats, merged,
                                       Nsplit, VC, C);
    }

    // Stream A: clear -> build -> row join.
    clear_all<<<592, B>>>(dsm, Nd);
    int mblocks = (M + B - 1) / B;
    int dblocks = (Nd + B - 1) / B;
    build_all<<<mblocks + dblocks, B>>>(mask_coords, M, ds_coords, Nd, mblocks);
    row_kernel<<<(N + B - 1) / B, B>>>(x_coords, mask_scores, merged, dsm, N, C);

    // Join, then the main streaming kernel.
    cudaEventRecord(e_join, s_b);
    cudaStreamWaitEvent(0, e_join, 0);

    long long total = (long long)N * VC;
    int blocks = (int)((total + B - 1) / B);
    feat_kernel<<<blocks, B>>>((const float4*)x_feats, (float4*)pruned,
                               (float4*)scaled, merged, N, VC, C, Nsplit);
}

// round 12
// speedup vs baseline: 1.0131x; 1.0131x over previous
#include <cuda_runtime.h>
#include <stdint.h>

// =============================================================================
// key32 = int32-wrapped reference key: (b&3)<<30 | x<<20 | y<<10 | z.
// Packed hash entry (8B): key32<<32 | index. atomicMin == min-index per key.
// EMPTY 0xFF..F unreachable (key bit 29 always 0 for coords < 512).
//
// Pipeline (graph fork-join, R10 lesson applied):
//   stream B: merged_copy rows [0, Nsplit), Nsplit=3N/8 (~96MB, fits the
//             ~40us clear+build low-BW window)
//   stream A: clear -> build ; JOIN B HERE ; row join ; feat
//   feat: pruned+scaled all rows, merged[:,2:] only rows >= Nsplit
// =============================================================================

#define MASK_CAP (1u << 22)
#define DS_CAP   (1u << 19)
#define EMPTY64  0xFFFFFFFFFFFFFFFFull

__device__ unsigned long long g_mtab[MASK_CAP];
__device__ unsigned long long g_dtab[DS_CAP];
__device__ float2             g_rowinfo[1100000];

__device__ __forceinline__ uint32_t key32_of(int4 c) {
    return ((uint32_t)c.x << 30) | ((uint32_t)c.y << 20) |
           ((uint32_t)c.z << 10) | (uint32_t)c.w;
}

__device__ __forceinline__ uint32_t hash32(uint32_t k) {
    k ^= k >> 16; k *= 0x85ebca6bu;
    k ^= k >> 13; k *= 0xc2b2ae35u;
    k ^= k >> 16;
    return k;
}

__global__ void clear_all(float* __restrict__ dsm, int Nd) {
    int t = blockIdx.x * blockDim.x + threadIdx.x;
    int stride = gridDim.x * blockDim.x;
    ulonglong2 ff = make_ulonglong2(EMPTY64, EMPTY64);
    for (int s = t; s < (int)(MASK_CAP / 2); s += stride)
        ((ulonglong2*)g_mtab)[s] = ff;
    for (int s = t; s < (int)(DS_CAP / 2); s += stride)
        ((ulonglong2*)g_dtab)[s] = ff;
    float4 z = make_float4(0.f, 0.f, 0.f, 0.f);
    for (int s = t; s < Nd / 4; s += stride)
        ((float4*)dsm)[s] = z;
    int tail = (Nd / 4) * 4;
    if (t < Nd - tail) dsm[tail + t] = 0.f;
}

__device__ __forceinline__ void insert(unsigned long long* __restrict__ tab,
                                       uint32_t k, int i, uint32_t capmask) {
    unsigned long long desired = ((unsigned long long)k << 32) | (uint32_t)i;
    uint32_t slot = hash32(k) & capmask;
    while (true) {
        unsigned long long prev = atomicCAS(&tab[slot], EMPTY64, desired);
        if (prev == EMPTY64) break;
        if ((uint32_t)(prev >> 32) == k) {
            atomicMin(&tab[slot], desired);
            break;
        }
        slot = (slot + 1) & capmask;
    }
}

__global__ void build_all(const int4* __restrict__ mask_coords, int M,
                          const int4* __restrict__ ds_coords, int Nd,
                          int mblocks) {
    if ((int)blockIdx.x < mblocks) {
        int i = blockIdx.x * blockDim.x + threadIdx.x;
        if (i >= M) return;
        insert(g_mtab, key32_of(mask_coords[i]), i, MASK_CAP - 1);
    } else {
        int i = (blockIdx.x - mblocks) * blockDim.x + threadIdx.x;
        if (i >= Nd) return;
        insert(g_dtab, key32_of(ds_coords[i]), i, DS_CAP - 1);
    }
}

// ---- Early merged-feature copy (rows [0, Nsplit)) on the forked stream ----
__global__ void merged_copy(const float4* __restrict__ x_feats,
                            float* __restrict__ merged,
                            int Nsplit, int VC, int C) {
    long long t = (long long)blockIdx.x * blockDim.x + threadIdx.x;
    long long total = (long long)Nsplit * VC;
    if (t >= total) return;
    int i = (int)(t / VC);
    int j = (int)(t % VC);
    float4 f = x_feats[t];
    float2* m = (float2*)(merged + (size_t)i * (size_t)(C + 2) + 2 + (size_t)j * 4);
    m[0] = make_float2(f.x, f.y);
    m[1] = make_float2(f.z, f.w);
}

__global__ void row_kernel(const int4* __restrict__ x_coords,
                           const float2* __restrict__ mask_scores,
                           float* __restrict__ merged,
                           float* __restrict__ ds_mask,
                           int N, int C) {
    int i = blockIdx.x * blockDim.x + threadIdx.x;
    if (i >= N) return;
    int4 c = x_coords[i];
    uint32_t k = key32_of(c);
    float s0 = 0.0f, s1 = 0.0f;
    uint32_t slot = hash32(k) & (MASK_CAP - 1);
    while (true) {
        unsigned long long e = __ldg(&g_mtab[slot]);
        if ((uint32_t)(e >> 32) == k) {
            float2 msv = __ldg(&mask_scores[(uint32_t)e]);
            s0 = msv.x; s1 = msv.y;
            break;
        }
        if (e == EMPTY64) break;
        slot = (slot + 1) & (MASK_CAP - 1);
    }
    float attn = (s1 > 0.5f) ? 1.0f : 0.0f;
    g_rowinfo[i] = make_float2(attn, s1 * attn);
    *(float2*)(merged + (size_t)i * (size_t)(C + 2)) = make_float2(s0, s1);
    if (attn > 0.0f) {
        int4 p = make_int4(c.x, c.y >> 1, c.z >> 1, c.w >> 1);
        uint32_t pk = key32_of(p);
        uint32_t ds = hash32(pk) & (DS_CAP - 1);
        while (true) {
            unsigned long long e = __ldg(&g_dtab[ds]);
            if ((uint32_t)(e >> 32) == pk) { ds_mask[(uint32_t)e] = 1.0f; break; }
            if (e == EMPTY64) break;
            ds = (ds + 1) & (DS_CAP - 1);
        }
    }
}

// ---- Main stream: pruned+scaled all rows; merged only i >= Nsplit ---------
__global__ void feat_kernel(const float4* __restrict__ x_feats,
                            float4* __restrict__ pruned,
                            float4* __restrict__ scaled,
                            float* __restrict__ merged,
                            int N, int VC, int C, int Nsplit) {
    long long t = (long long)blockIdx.x * blockDim.x + threadIdx.x;
    long long total = (long long)N * VC;
    if (t >= total) return;
    int i = (int)(t / VC);
    int j = (int)(t % VC);
    float4 f = x_feats[t];
    float2 rs = g_rowinfo[i];
    pruned[t] = make_float4(f.x * rs.x, f.y * rs.x, f.z * rs.x, f.w * rs.x);
    scaled[t] = make_float4(f.x * rs.y, f.y * rs.y, f.z * rs.y, f.w * rs.y);
    if (i >= Nsplit) {
        float2* m = (float2*)(merged + (size_t)i * (size_t)(C + 2) + 2
                              + (size_t)j * 4);
        m[0] = make_float2(f.x, f.y);
        m[1] = make_float2(f.z, f.w);
    }
}

// ---------------- Launch ----------------------------------------------------
extern "C" void kernel_launch(void* const* d_in, const int* in_sizes, int n_in,
                              void* d_out, int out_size) {
    const int4*   x_coords    = (const int4*)d_in[0];
    const float*  x_feats     = (const float*)d_in[1];
    const int4*   mask_coords = (const int4*)d_in[2];
    const float2* mask_scores = (const float2*)d_in[3];
    const int4*   ds_coords   = (const int4*)d_in[4];

    int N  = in_sizes[0] / 4;
    int C  = in_sizes[1] / N;
    int M  = in_sizes[2] / 4;
    int Nd = in_sizes[4] / 4;
    int VC = C / 4;

    float* out    = (float*)d_out;
    float* pruned = out;
    float* scaled = out + (size_t)N * C;
    float* merged = out + (size_t)2 * N * C;
    float* dsm    = merged + (size_t)N * (C + 2);

    static cudaStream_t s_b = nullptr;
    static cudaEvent_t  e_fork = nullptr, e_join = nullptr;
    if (s_b == nullptr) {
        cudaStreamCreateWithFlags(&s_b, cudaStreamNonBlocking);
        cudaEventCreateWithFlags(&e_fork, cudaEventDisableTiming);
        cudaEventCreateWithFlags(&e_join, cudaEventDisableTiming);
    }

    const int B = 256;
    int Nsplit = (3 * (N / 8)) & ~63;   // ~37.5% of rows, ~96MB copy

    // Fork: small early merged copy on stream B (fits clear+build window).
    cudaEventRecord(e_fork, 0);
    cudaStreamWaitEvent(s_b, e_fork, 0);
    {
        long long tB = (long long)Nsplit * VC;
        int gB = (int)((tB + B - 1) / B);
        merged_copy<<<gB, B, 0, s_b>>>((const float4*)x_feats, merged,
                                       Nsplit, VC, C);
    }

    // Stream A: clear -> build.
    clear_all<<<592, B>>>(dsm, Nd);
    int mblocks = (M + B - 1) / B;
    int dblocks = (Nd + B - 1) / B;
    build_all<<<mblocks + dblocks, B>>>(mask_coords, M, ds_coords, Nd, mblocks);

    // Join BEFORE the bandwidth-hungry phases (R10 lesson: no copy/row overlap).
    cudaEventRecord(e_join, s_b);
    cudaStreamWaitEvent(0, e_join, 0);

    row_kernel<<<(N + B - 1) / B, B>>>(x_coords, mask_scores, merged, dsm, N, C);

    long long total = (long long)N * VC;
    int blocks = (int)((total + B - 1) / B);
    feat_kernel<<<blocks, B>>>((const float4*)x_feats, (float4*)pruned,
                               (float4*)scaled, merged, N, VC, C, Nsplit);
}

// round 13
// speedup vs baseline: 1.2985x; 1.2817x over previous
#include <cuda_runtime.h>
#include <stdint.h>

// =============================================================================
// key32 = int32-wrapped reference key: (b&3)<<30 | x<<20 | y<<10 | z.
// Packed hash entry (8B): key32<<32 | index. atomicMin == min-index per key.
// EMPTY 0xFF..F unreachable (key bit 29 always 0 for coords < 512).
//
// R12: single stream (overlap removed — regressed twice). row_kernel no longer
// writes merged[:,0:2] (was ~128MB of write-allocate on scattered 8B stores);
// feat's row-leader thread writes it on a line it already owns.
// =============================================================================

#define MASK_CAP (1u << 22)
#define DS_CAP   (1u << 19)
#define EMPTY64  0xFFFFFFFFFFFFFFFFull

__device__ unsigned long long g_mtab[MASK_CAP];
__device__ unsigned long long g_dtab[DS_CAP];
__device__ float4             g_rowinfo[1100000];   // (s0, s1, attn, attn*s1)

__device__ __forceinline__ uint32_t key32_of(int4 c) {
    return ((uint32_t)c.x << 30) | ((uint32_t)c.y << 20) |
           ((uint32_t)c.z << 10) | (uint32_t)c.w;
}

__device__ __forceinline__ uint32_t hash32(uint32_t k) {
    k ^= k >> 16; k *= 0x85ebca6bu;
    k ^= k >> 13; k *= 0xc2b2ae35u;
    k ^= k >> 16;
    return k;
}

__global__ void clear_all(float* __restrict__ dsm, int Nd) {
    int t = blockIdx.x * blockDim.x + threadIdx.x;
    int stride = gridDim.x * blockDim.x;
    ulonglong2 ff = make_ulonglong2(EMPTY64, EMPTY64);
    for (int s = t; s < (int)(MASK_CAP / 2); s += stride)
        ((ulonglong2*)g_mtab)[s] = ff;
    for (int s = t; s < (int)(DS_CAP / 2); s += stride)
        ((ulonglong2*)g_dtab)[s] = ff;
    float4 z = make_float4(0.f, 0.f, 0.f, 0.f);
    for (int s = t; s < Nd / 4; s += stride)
        ((float4*)dsm)[s] = z;
    int tail = (Nd / 4) * 4;
    if (t < Nd - tail) dsm[tail + t] = 0.f;
}

__device__ __forceinline__ void insert(unsigned long long* __restrict__ tab,
                                       uint32_t k, int i, uint32_t capmask) {
    unsigned long long desired = ((unsigned long long)k << 32) | (uint32_t)i;
    uint32_t slot = hash32(k) & capmask;
    while (true) {
        unsigned long long prev = atomicCAS(&tab[slot], EMPTY64, desired);
        if (prev == EMPTY64) break;
        if ((uint32_t)(prev >> 32) == k) {    // duplicate key -> keep min idx
            atomicMin(&tab[slot], desired);
            break;
        }
        slot = (slot + 1) & capmask;
    }
}

__global__ void build_all(const int4* __restrict__ mask_coords, int M,
                          const int4* __restrict__ ds_coords, int Nd,
                          int mblocks) {
    if ((int)blockIdx.x < mblocks) {
        int i = blockIdx.x * blockDim.x + threadIdx.x;
        if (i >= M) return;
        insert(g_mtab, key32_of(mask_coords[i]), i, MASK_CAP - 1);
    } else {
        int i = (blockIdx.x - mblocks) * blockDim.x + threadIdx.x;
        if (i >= Nd) return;
        insert(g_dtab, key32_of(ds_coords[i]), i, DS_CAP - 1);
    }
}

// ---------------- Row kernel: join + rowinfo + ds scatter (NO merged) ------
__global__ void row_kernel(const int4* __restrict__ x_coords,
                           const float2* __restrict__ mask_scores,
                           float* __restrict__ ds_mask,
                           int N) {
    int i = blockIdx.x * blockDim.x + threadIdx.x;
    if (i >= N) return;
    int4 c = x_coords[i];
    uint32_t k = key32_of(c);
    float s0 = 0.0f, s1 = 0.0f;
    uint32_t slot = hash32(k) & (MASK_CAP - 1);
    while (true) {
        unsigned long long e = __ldg(&g_mtab[slot]);
        if ((uint32_t)(e >> 32) == k) {
            float2 msv = __ldg(&mask_scores[(uint32_t)e]);
            s0 = msv.x; s1 = msv.y;
            break;
        }
        if (e == EMPTY64) break;
        slot = (slot + 1) & (MASK_CAP - 1);
    }
    float attn = (s1 > 0.5f) ? 1.0f : 0.0f;
    g_rowinfo[i] = make_float4(s0, s1, attn, s1 * attn);
    if (attn > 0.0f) {
        int4 p = make_int4(c.x, c.y >> 1, c.z >> 1, c.w >> 1);
        uint32_t pk = key32_of(p);
        uint32_t ds = hash32(pk) & (DS_CAP - 1);
        while (true) {
            unsigned long long e = __ldg(&g_dtab[ds]);
            if ((uint32_t)(e >> 32) == pk) { ds_mask[(uint32_t)e] = 1.0f; break; }
            if (e == EMPTY64) break;
            ds = (ds + 1) & (DS_CAP - 1);
        }
    }
}

// ---------------- Feature kernel: full stream, leader writes merged[:,0:2] -
__global__ void feat_kernel(const float4* __restrict__ x_feats,
                            float4* __restrict__ pruned,
                            float4* __restrict__ scaled,
                            float* __restrict__ merged,
                            int N, int VC, int C) {
    long long t = (long long)blockIdx.x * blockDim.x + threadIdx.x;
    long long total = (long long)N * VC;
    if (t >= total) return;
    int i = (int)(t / VC);
    int j = (int)(t % VC);
    float4 f = x_feats[t];
    float4 rs = g_rowinfo[i];   // (s0, s1, attn, attn*s1)
    pruned[t] = make_float4(f.x * rs.z, f.y * rs.z, f.z * rs.z, f.w * rs.z);
    scaled[t] = make_float4(f.x * rs.w, f.y * rs.w, f.z * rs.w, f.w * rs.w);
    float* mrow = merged + (size_t)i * (size_t)(C + 2);
    if (j == 0)
        *(float2*)mrow = make_float2(rs.x, rs.y);   // same line as j==0 stores
    float2* m = (float2*)(mrow + 2 + (size_t)j * 4);
    m[0] = make_float2(f.x, f.y);
    m[1] = make_float2(f.z, f.w);
}

// ---------------- Launch ----------------------------------------------------
extern "C" void kernel_launch(void* const* d_in, const int* in_sizes, int n_in,
                              void* d_out, int out_size) {
    const int4*   x_coords    = (const int4*)d_in[0];
    const float*  x_feats     = (const float*)d_in[1];
    const int4*   mask_coords = (const int4*)d_in[2];
    const float2* mask_scores = (const float2*)d_in[3];
    const int4*   ds_coords   = (const int4*)d_in[4];

    int N  = in_sizes[0] / 4;
    int C  = in_sizes[1] / N;
    int M  = in_sizes[2] / 4;
    int Nd = in_sizes[4] / 4;
    int VC = C / 4;

    float* out    = (float*)d_out;
    float* pruned = out;
    float* scaled = out + (size_t)N * C;
    float* merged = out + (size_t)2 * N * C;
    float* dsm    = merged + (size_t)N * (C + 2);

    const int B = 256;
    clear_all<<<592, B>>>(dsm, Nd);

    int mblocks = (M + B - 1) / B;
    int dblocks = (Nd + B - 1) / B;
    build_all<<<mblocks + dblocks, B>>>(mask_coords, M, ds_coords, Nd, mblocks);

    row_kernel<<<(N + B - 1) / B, B>>>(x_coords, mask_scores, dsm, N);

    long long total = (long long)N * VC;
    int blocks = (int)((total + B - 1) / B);
    feat_kernel<<<blocks, B>>>((const float4*)x_feats, (float4*)pruned,
                               (float4*)scaled, merged, N, VC, C);
}